// round 7
// baseline (speedup 1.0000x reference)
#include <cuda_runtime.h>
#include <cuda_bf16.h>
#include <cstdint>

#define N_NODES 100000
#define N_EDGES 1600000
#define F_IN 5
#define F_HID 64
#define F_OUT 72
#define NEG_SLOPE 0.2f

#define EPT 8                               // edges per thread in fused kBC
#define NT_BC 256
#define NB_BC ((N_EDGES / EPT + NT_BC - 1) / NT_BC)   // 782 blocks, all co-resident

// ---------------- device scratch (static, no allocation) ----------------
__device__ float g_as[N_NODES];       // x[n] . (W @ att_src)
__device__ float g_ad[N_NODES];       // x[n] . (W @ att_dst)
__device__ float g_denom[N_NODES];    // softmax denom per dst (init = self-loop exp)
__device__ float g_selfexp[N_NODES];  // self-loop exp term
__device__ float g_w[N_NODES];        // sum of alpha over edges with src = n
__device__ float g_pool5[F_IN];       // sum_n w_total[n] * x[n, :]
__device__ int   g_idx32;             // 1 if edge_index arrived as int32
__device__ unsigned g_arrive = 0;     // grid-barrier arrive counter
__device__ volatile unsigned g_release = 0;  // grid-barrier epoch (monotonic)

// ---------------- Kernel A: per-node attention halves + init ----------------
__global__ void kA(const float* __restrict__ x,
                   const float* __restrict__ W,
                   const float* __restrict__ att_src,
                   const float* __restrict__ att_dst,
                   const void*  __restrict__ ei) {
    __shared__ float ws[F_IN], wd[F_IN];
    int tid = threadIdx.x;
    if (tid < F_IN) {
        float s = 0.f, d = 0.f;
#pragma unroll
        for (int f = 0; f < F_HID; f++) {
            float w = W[tid * F_HID + f];
            s += w * att_src[f];
            d += w * att_dst[f];
        }
        ws[tid] = s; wd[tid] = d;
    }
    if (blockIdx.x == 0) {
        if (tid < F_IN) g_pool5[tid] = 0.0f;
        if (tid == 32) {
            // dtype sniff: int32 data read as int64 gives values >= 2^32 or < 0
            const long long* e64 = (const long long*)ei;
            int flag = 0;
            for (int i = 0; i < 64; i++) {
                long long v = e64[i];
                if (v < 0 || v >= (long long)N_NODES) flag = 1;
            }
            g_idx32 = flag;
        }
    }
    __syncthreads();

    int n = blockIdx.x * blockDim.x + tid;
    if (n >= N_NODES) return;

    const float* xr = x + (size_t)n * F_IN;
    float x0 = xr[0], x1 = xr[1], x2 = xr[2], x3 = xr[3], x4 = xr[4];
    float as = x0*ws[0] + x1*ws[1] + x2*ws[2] + x3*ws[3] + x4*ws[4];
    float ad = x0*wd[0] + x1*wd[1] + x2*wd[2] + x3*wd[3] + x4*wd[4];
    g_as[n] = as;
    g_ad[n] = ad;
    float es = as + ad;
    es = es > 0.0f ? es : NEG_SLOPE * es;   // LeakyReLU
    float se = __expf(es);
    g_denom[n]   = se;                       // denom starts with self-loop term
    g_selfexp[n] = se;
    g_w[n]       = 0.0f;
}

// ---------------- software grid barrier (all blocks co-resident) ----------------
__device__ __forceinline__ void grid_barrier(unsigned nblocks) {
    __syncthreads();
    if (threadIdx.x == 0) {
        __threadfence();                           // phase-1 atomics visible
        unsigned epoch = g_release;                // all blocks read same epoch
        __threadfence();                           // order read before arrive
        unsigned old = atomicAdd(&g_arrive, 1u);
        if (old == nblocks - 1u) {
            g_arrive = 0;                          // reset before release
            __threadfence();
            g_release = epoch + 1u;                // monotonic: replay-safe
        } else {
            while (g_release == epoch) __nanosleep(64);
        }
        __threadfence();                           // acquire
    }
    __syncthreads();
}

// ---------------- Kernel BC: fused edge passes, state in registers ----------------
__global__ void __launch_bounds__(NT_BC, 6)
kBC(const void* __restrict__ ei) {
    int t = blockIdx.x * NT_BC + threadIdx.x;
    int e0 = t * EPT;
    bool valid = (e0 < N_EDGES);            // N_EDGES % EPT == 0 -> all-or-nothing

    int s[EPT], d[EPT];
    float ex[EPT];

    if (valid) {
        if (g_idx32) {
            const int* b = (const int*)ei;
#pragma unroll
            for (int q = 0; q < EPT / 4; q++) {
                int4 sv = *(const int4*)(b + e0 + q * 4);
                int4 dv = *(const int4*)(b + N_EDGES + e0 + q * 4);
                s[q*4+0] = sv.x; s[q*4+1] = sv.y; s[q*4+2] = sv.z; s[q*4+3] = sv.w;
                d[q*4+0] = dv.x; d[q*4+1] = dv.y; d[q*4+2] = dv.z; d[q*4+3] = dv.w;
            }
        } else {
            const long long* b = (const long long*)ei;
#pragma unroll
            for (int q = 0; q < EPT / 2; q++) {
                ulonglong2 sv = *(const ulonglong2*)(b + e0 + q * 2);
                ulonglong2 dv = *(const ulonglong2*)(b + N_EDGES + e0 + q * 2);
                s[q*2+0] = (int)sv.x; s[q*2+1] = (int)sv.y;
                d[q*2+0] = (int)dv.x; d[q*2+1] = (int)dv.y;
            }
        }
        // phase 1: exp(leaky(as[s]+ad[d])) -> denom[d]
        float asv[EPT], adv[EPT];
#pragma unroll
        for (int i = 0; i < EPT; i++) { asv[i] = g_as[s[i]]; adv[i] = g_ad[d[i]]; }
#pragma unroll
        for (int i = 0; i < EPT; i++) {
            float ev = asv[i] + adv[i];
            ev = ev > 0.0f ? ev : NEG_SLOPE * ev;
            ex[i] = __expf(ev);
        }
#pragma unroll
        for (int i = 0; i < EPT; i++) atomicAdd(&g_denom[d[i]], ex[i]);
    }

    grid_barrier(gridDim.x);

    if (valid) {
        // phase 2: alpha = ex / denom[d] -> w[src]
        float dn[EPT];
#pragma unroll
        for (int i = 0; i < EPT; i++) dn[i] = g_denom[d[i]];
#pragma unroll
        for (int i = 0; i < EPT; i++)
            atomicAdd(&g_w[s[i]], ex[i] / (dn[i] + 1e-16f));
    }
}

// ---------------- Kernel D: pool5[k] = sum_n w_total[n] * x[n][k] ----------------
__global__ void kD(const float* __restrict__ x) {
    int n = blockIdx.x * blockDim.x + threadIdx.x;
    float acc[F_IN] = {0.f, 0.f, 0.f, 0.f, 0.f};
    if (n < N_NODES) {
        float wn = g_w[n] + g_selfexp[n] / (g_denom[n] + 1e-16f);
        const float* xr = x + (size_t)n * F_IN;
#pragma unroll
        for (int k = 0; k < F_IN; k++) acc[k] = wn * xr[k];
    }
#pragma unroll
    for (int k = 0; k < F_IN; k++)
#pragma unroll
        for (int o = 16; o > 0; o >>= 1)
            acc[k] += __shfl_xor_sync(0xffffffffu, acc[k], o);

    __shared__ float s[8][F_IN];
    int warp = threadIdx.x >> 5, lane = threadIdx.x & 31;
    if (lane < F_IN) s[warp][lane] = acc[lane];
    __syncthreads();
    if (threadIdx.x < F_IN) {
        float v = 0.f;
#pragma unroll
        for (int wdx = 0; wdx < 8; wdx++) v += s[wdx][threadIdx.x];
        atomicAdd(&g_pool5[threadIdx.x], v);
    }
}

// ---------------- Kernel E: pool5 -> pooled64 -> FC -> ReLU ----------------
__global__ void kE(const float* __restrict__ W,
                   const float* __restrict__ b_gat,
                   const float* __restrict__ W_fc,
                   const float* __restrict__ b_fc,
                   float* __restrict__ out) {
    __shared__ float p64[F_HID];
    int t = threadIdx.x;
    if (t < F_HID) {
        float acc = b_gat[t];
        const float invN = 1.0f / (float)N_NODES;
#pragma unroll
        for (int k = 0; k < F_IN; k++)
            acc += (g_pool5[k] * invN) * W[k * F_HID + t];
        p64[t] = acc;
    }
    __syncthreads();
    if (t < F_OUT) {
        float acc = b_fc[t];
#pragma unroll
        for (int f = 0; f < F_HID; f++) acc += p64[f] * W_fc[f * F_OUT + t];
        out[t] = fmaxf(acc, 0.0f);
    }
}

// ---------------- launch ----------------
extern "C" void kernel_launch(void* const* d_in, const int* in_sizes, int n_in,
                              void* d_out, int out_size) {
    const float* x       = (const float*)d_in[0];
    const void*  ei      = d_in[1];
    const float* W       = (const float*)d_in[2];
    const float* att_src = (const float*)d_in[3];
    const float* att_dst = (const float*)d_in[4];
    const float* b_gat   = (const float*)d_in[5];
    const float* W_fc    = (const float*)d_in[6];
    const float* b_fc    = (const float*)d_in[7];
    float* out = (float*)d_out;

    int blocksN = (N_NODES + 255) / 256;

    kA<<<blocksN, 256>>>(x, W, att_src, att_dst, ei);
    kBC<<<NB_BC, NT_BC>>>(ei);
    kD<<<blocksN, 256>>>(x);
    kE<<<1, 128>>>(W, b_gat, W_fc, b_fc, out);
}

// round 8
// speedup vs baseline: 1.2251x; 1.2251x over previous
#include <cuda_runtime.h>
#include <cuda_bf16.h>
#include <cstdint>

#define N_NODES 100000
#define N_EDGES 1600000
#define F_IN 5
#define F_HID 64
#define F_OUT 72
#define NEG_SLOPE 0.2f

// ---------------- device scratch (static, no allocation) ----------------
__device__ float g_as[N_NODES];       // x[n] . (W @ att_src)
__device__ float g_ad[N_NODES];       // x[n] . (W @ att_dst)
__device__ float g_denom[N_NODES];    // softmax denom per dst (init = self-loop exp)
__device__ float g_selfexp[N_NODES];  // self-loop exp term
__device__ float g_w[N_NODES];        // sum of alpha over edges with src = n
__device__ float g_ex[N_EDGES];       // per-edge exp   (kB -> kC stream)
__device__ int   g_s32[N_EDGES];      // per-edge src32 (kB -> kC stream)
__device__ int   g_d32[N_EDGES];      // per-edge dst32 (kB -> kC stream)
__device__ float g_pool5[F_IN];       // sum_n w_total[n] * x[n, :]
__device__ int   g_idx32;             // 1 if edge_index arrived as int32

// ---------------- Kernel A: per-node attention halves + init ----------------
__global__ void kA(const float* __restrict__ x,
                   const float* __restrict__ W,
                   const float* __restrict__ att_src,
                   const float* __restrict__ att_dst,
                   const void*  __restrict__ ei,
                   const float* __restrict__ W_fc) {
    __shared__ float ws[F_IN], wd[F_IN];
    int tid = threadIdx.x;
    if (tid < F_IN) {
        float s = 0.f, d = 0.f;
#pragma unroll
        for (int f = 0; f < F_HID; f++) {
            float w = W[tid * F_HID + f];
            s += w * att_src[f];
            d += w * att_dst[f];
        }
        ws[tid] = s; wd[tid] = d;
    }
    if (blockIdx.x == 0) {
        if (tid < F_IN) g_pool5[tid] = 0.0f;
        if (tid == 32) {
            // dtype sniff: int32 data read as int64 gives values >= 2^32 or < 0
            const long long* e64 = (const long long*)ei;
            int flag = 0;
            for (int i = 0; i < 64; i++) {
                long long v = e64[i];
                if (v < 0 || v >= (long long)N_NODES) flag = 1;
            }
            g_idx32 = flag;
        }
    }
    if (blockIdx.x == 1) {
        // warm L2 with the FC weights so the tail kernel doesn't eat DRAM latency
        const char* p = (const char*)W_fc;
        int bytes = F_HID * F_OUT * 4;
        for (int off = tid * 128; off < bytes; off += blockDim.x * 128)
            asm volatile("prefetch.global.L2 [%0];" :: "l"(p + off));
    }
    __syncthreads();

    int n = blockIdx.x * blockDim.x + tid;
    if (n >= N_NODES) return;

    const float* xr = x + (size_t)n * F_IN;
    float x0 = xr[0], x1 = xr[1], x2 = xr[2], x3 = xr[3], x4 = xr[4];
    float as = x0*ws[0] + x1*ws[1] + x2*ws[2] + x3*ws[3] + x4*ws[4];
    float ad = x0*wd[0] + x1*wd[1] + x2*wd[2] + x3*wd[3] + x4*wd[4];
    g_as[n] = as;
    g_ad[n] = ad;
    float es = as + ad;
    es = es > 0.0f ? es : NEG_SLOPE * es;   // LeakyReLU
    float se = __expf(es);
    g_denom[n]   = se;                       // denom starts with self-loop term
    g_selfexp[n] = se;
    g_w[n]       = 0.0f;
}

// ---------------- Kernel B: decode edges once, exp -> streams + denom atomics ----------------
__global__ void kB(const void* __restrict__ ei) {
    int e0 = (blockIdx.x * blockDim.x + threadIdx.x) * 4;
    if (e0 >= N_EDGES) return;
    int s[4], d[4];
    if (g_idx32) {
        const int* b = (const int*)ei;
        int4 sv = __ldcs((const int4*)(b + e0));
        int4 dv = __ldcs((const int4*)(b + N_EDGES + e0));
        s[0] = sv.x; s[1] = sv.y; s[2] = sv.z; s[3] = sv.w;
        d[0] = dv.x; d[1] = dv.y; d[2] = dv.z; d[3] = dv.w;
    } else {
        const long long* b = (const long long*)ei;
        ulonglong2 sa = __ldcs((const ulonglong2*)(b + e0));
        ulonglong2 sb = __ldcs((const ulonglong2*)(b + e0 + 2));
        ulonglong2 da = __ldcs((const ulonglong2*)(b + N_EDGES + e0));
        ulonglong2 db = __ldcs((const ulonglong2*)(b + N_EDGES + e0 + 2));
        s[0] = (int)sa.x; s[1] = (int)sa.y; s[2] = (int)sb.x; s[3] = (int)sb.y;
        d[0] = (int)da.x; d[1] = (int)da.y; d[2] = (int)db.x; d[3] = (int)db.y;
    }

    float asv[4], adv[4];
#pragma unroll
    for (int i = 0; i < 4; i++) { asv[i] = g_as[s[i]]; adv[i] = g_ad[d[i]]; }

    float ex[4];
#pragma unroll
    for (int i = 0; i < 4; i++) {
        float ev = asv[i] + adv[i];
        ev = ev > 0.0f ? ev : NEG_SLOPE * ev;
        ex[i] = __expf(ev);
    }
    *(float4*)&g_ex[e0]  = make_float4(ex[0], ex[1], ex[2], ex[3]);
    *(int4*)&g_s32[e0]   = make_int4(s[0], s[1], s[2], s[3]);
    *(int4*)&g_d32[e0]   = make_int4(d[0], d[1], d[2], d[3]);
#pragma unroll
    for (int i = 0; i < 4; i++) atomicAdd(&g_denom[d[i]], ex[i]);
}

// ---------------- Kernel C: alpha = ex/denom[dst] -> w[src] atomics ----------------
__global__ void kC() {
    int e0 = (blockIdx.x * blockDim.x + threadIdx.x) * 4;
    if (e0 >= N_EDGES) return;

    int4   sv  = *(const int4*)&g_s32[e0];
    int4   dv  = *(const int4*)&g_d32[e0];
    float4 exv = *(const float4*)&g_ex[e0];

    int   s[4]  = {sv.x, sv.y, sv.z, sv.w};
    int   d[4]  = {dv.x, dv.y, dv.z, dv.w};
    float ex[4] = {exv.x, exv.y, exv.z, exv.w};

    float dn[4];
#pragma unroll
    for (int i = 0; i < 4; i++) dn[i] = g_denom[d[i]];
#pragma unroll
    for (int i = 0; i < 4; i++)
        atomicAdd(&g_w[s[i]], ex[i] / (dn[i] + 1e-16f));
}

// ---------------- Kernel D: pool5[k] = sum_n w_total[n] * x[n][k] ----------------
__global__ void kD(const float* __restrict__ x) {
    int n = blockIdx.x * blockDim.x + threadIdx.x;
    float acc[F_IN] = {0.f, 0.f, 0.f, 0.f, 0.f};
    if (n < N_NODES) {
        float wn = g_w[n] + g_selfexp[n] / (g_denom[n] + 1e-16f);
        const float* xr = x + (size_t)n * F_IN;
#pragma unroll
        for (int k = 0; k < F_IN; k++) acc[k] = wn * xr[k];
    }
#pragma unroll
    for (int k = 0; k < F_IN; k++)
#pragma unroll
        for (int o = 16; o > 0; o >>= 1)
            acc[k] += __shfl_xor_sync(0xffffffffu, acc[k], o);

    __shared__ float s[8][F_IN];
    int warp = threadIdx.x >> 5, lane = threadIdx.x & 31;
    if (lane < F_IN) s[warp][lane] = acc[lane];
    __syncthreads();
    if (threadIdx.x < F_IN) {
        float v = 0.f;
#pragma unroll
        for (int wdx = 0; wdx < 8; wdx++) v += s[wdx][threadIdx.x];
        atomicAdd(&g_pool5[threadIdx.x], v);
    }
}

// ---------------- Kernel E: pool5 -> pooled64 -> FC -> ReLU (parallel) ----------------
// 576 threads = 72 outputs x 8-lane dot-product groups.
__global__ void kE(const float* __restrict__ W,
                   const float* __restrict__ b_gat,
                   const float* __restrict__ W_fc,
                   const float* __restrict__ b_fc,
                   float* __restrict__ out) {
    __shared__ float p64[F_HID];
    int t = threadIdx.x;
    if (t < F_HID) {
        float acc = b_gat[t];
        const float invN = 1.0f / (float)N_NODES;
#pragma unroll
        for (int k = 0; k < F_IN; k++)
            acc += (g_pool5[k] * invN) * W[k * F_HID + t];
        p64[t] = acc;
    }
    __syncthreads();

    int o    = t >> 3;            // output index 0..71
    int lane = t & 7;             // 8-lane group
    if (o < F_OUT) {
        float acc = 0.0f;
#pragma unroll
        for (int f = lane; f < F_HID; f += 8)
            acc += p64[f] * W_fc[f * F_OUT + o];   // coalesced across o
#pragma unroll
        for (int off = 4; off > 0; off >>= 1)
            acc += __shfl_down_sync(0xffffffffu, acc, off, 8);
        if (lane == 0) out[o] = fmaxf(acc + b_fc[o], 0.0f);
    }
}

// ---------------- launch ----------------
extern "C" void kernel_launch(void* const* d_in, const int* in_sizes, int n_in,
                              void* d_out, int out_size) {
    const float* x       = (const float*)d_in[0];
    const void*  ei      = d_in[1];
    const float* W       = (const float*)d_in[2];
    const float* att_src = (const float*)d_in[3];
    const float* att_dst = (const float*)d_in[4];
    const float* b_gat   = (const float*)d_in[5];
    const float* W_fc    = (const float*)d_in[6];
    const float* b_fc    = (const float*)d_in[7];
    float* out = (float*)d_out;

    int blocksN = (N_NODES + 255) / 256;
    int blocksE = (N_EDGES / 4 + 255) / 256;

    kA<<<blocksN, 256>>>(x, W, att_src, att_dst, ei, W_fc);
    kB<<<blocksE, 256>>>(ei);
    kC<<<blocksE, 256>>>();
    kD<<<blocksN, 256>>>(x);
    kE<<<1, 576>>>(W, b_gat, W_fc, b_fc, out);
}